// round 7
// baseline (speedup 1.0000x reference)
#include <cuda_runtime.h>

#define NN 20000
#define NE 320000
#define NT (NN + NE)
#define C  128
#define H  4
#define HC 512
#define BM 64
#define BN 64
#define BK 64
#define NEG 0.2f

// ---------------- device scratch (static, 16B-aligned, no allocation) ----------------
__device__ __align__(16) float g_xh[NN * HC];   // transformed features [N,H,C] (per conv)
__device__ __align__(16) float g_h1[NN * C];    // conv1 output
__device__ __align__(16) float g_res[NN * C];   // residual conv output
__device__ __align__(16) float g_als[NN * H];
__device__ __align__(16) float g_ald[NN * H];
__device__ __align__(16) int   g_rowptr[NN + 1];
__device__ __align__(16) int   g_cnt[NN];
__device__ __align__(16) int   g_wp[NN];
__device__ __align__(16) int   g_col[NT];

// ---------------- CSR build (by dst), reused by all three convs ----------------
// NOTE: edge_index is int32 on device (JAX x64 is disabled by default, so the
// reference's jnp.int64 silently materializes as int32).
__global__ void k_zero_cnt(int n) {
    int i = blockIdx.x * blockDim.x + threadIdx.x;
    if (i < n) g_cnt[i] = 0;
}

__global__ void k_hist(const int* __restrict__ ei, int e, int n) {
    int i = blockIdx.x * blockDim.x + threadIdx.x;
    if (i >= e + n) return;
    int d = (i < e) ? ei[e + i] : (i - e);
    if ((unsigned)d < (unsigned)n) atomicAdd(&g_cnt[d], 1);
}

__global__ void k_scan(int n) {
    __shared__ int s[1024];
    __shared__ int carry;
    int tid = threadIdx.x;
    if (tid == 0) carry = 0;
    __syncthreads();
    for (int base = 0; base < n; base += 1024) {
        int i = base + tid;
        int v = (i < n) ? g_cnt[i] : 0;
        s[tid] = v;
        __syncthreads();
        for (int off = 1; off < 1024; off <<= 1) {
            int t = (tid >= off) ? s[tid - off] : 0;
            __syncthreads();
            s[tid] += t;
            __syncthreads();
        }
        int excl = s[tid] - v + carry;
        if (i < n) { g_rowptr[i] = excl; g_wp[i] = excl; }
        __syncthreads();
        if (tid == 1023) carry += s[1023];
        __syncthreads();
    }
    if (tid == 0) g_rowptr[n] = carry;
}

__global__ void k_scatter(const int* __restrict__ ei, int e, int n) {
    int i = blockIdx.x * blockDim.x + threadIdx.x;
    if (i >= e + n) return;
    int s, d;
    if (i < e) { s = ei[i]; d = ei[e + i]; }
    else       { s = i - e; d = s; }
    if ((unsigned)d >= (unsigned)n || (unsigned)s >= (unsigned)n) return;
    int pos = atomicAdd(&g_wp[d], 1);
    g_col[pos] = s;
}

// ---------------- SGEMM: g_xh[n, h*128+o] = sum_i A[n,i] * W[h,i,o] ----------------
// A: [M,128] row-major (external x, or g_h1 when asel=1). W: [H,128,128].
// Tile 64x64, BK=64, 33.8 KB STATIC smem, 256 threads, 4x4 micro-tile.
__global__ void __launch_bounds__(256) k_gemm(const float* __restrict__ Aext,
                                              const float* __restrict__ W,
                                              int M, int asel) {
    __shared__ float As[BM][BK + 4];   // +4 pad kills column-read bank conflicts
    __shared__ float Bs[BK][BN];
    const float* A = asel ? (const float*)g_h1 : Aext;

    int tid = threadIdx.x;
    int m0 = blockIdx.x * BM;
    int n0 = blockIdx.y * BN;
    const float* Wb = W + (n0 >> 7) * (C * C) + (n0 & 127);

    int tx = tid & 15;          // 16 col-groups of 4
    int ty = tid >> 4;          // 16 row-groups of 4
    float acc[4][4] = {};

    for (int kk = 0; kk < C; kk += BK) {
#pragma unroll
        for (int it = 0; it < 4; it++) {
            int q   = tid + it * 256;       // 0..1023
            int row = q >> 4;               // 64 rows
            int kc  = (q & 15) << 2;        // 16 float4 per row
            float4 v = make_float4(0.f, 0.f, 0.f, 0.f);
            if (m0 + row < M) v = *(const float4*)(A + (m0 + row) * C + kk + kc);
            *(float4*)(&As[row][kc]) = v;
        }
#pragma unroll
        for (int it = 0; it < 4; it++) {
            int q  = tid + it * 256;
            int k  = q >> 4;
            int nc = (q & 15) << 2;
            *(float4*)(&Bs[k][nc]) = *(const float4*)(Wb + (kk + k) * C + nc);
        }
        __syncthreads();

#pragma unroll 8
        for (int k = 0; k < BK; k++) {
            float4 b = *(const float4*)(&Bs[k][tx * 4]);
            float a0 = As[ty * 4 + 0][k];
            float a1 = As[ty * 4 + 1][k];
            float a2 = As[ty * 4 + 2][k];
            float a3 = As[ty * 4 + 3][k];
            acc[0][0] += a0 * b.x; acc[0][1] += a0 * b.y; acc[0][2] += a0 * b.z; acc[0][3] += a0 * b.w;
            acc[1][0] += a1 * b.x; acc[1][1] += a1 * b.y; acc[1][2] += a1 * b.z; acc[1][3] += a1 * b.w;
            acc[2][0] += a2 * b.x; acc[2][1] += a2 * b.y; acc[2][2] += a2 * b.z; acc[2][3] += a2 * b.w;
            acc[3][0] += a3 * b.x; acc[3][1] += a3 * b.y; acc[3][2] += a3 * b.z; acc[3][3] += a3 * b.w;
        }
        __syncthreads();
    }

#pragma unroll
    for (int i = 0; i < 4; i++) {
        int mrow = m0 + ty * 4 + i;
        if (mrow < M) {
            float4 o = make_float4(acc[i][0], acc[i][1], acc[i][2], acc[i][3]);
            *(float4*)(g_xh + mrow * HC + n0 + tx * 4) = o;
        }
    }
}

// ---------------- attention logits: als[n*H+h], ald[n*H+h] ----------------
__global__ void k_att(const float* __restrict__ a_src, const float* __restrict__ a_dst, int n) {
    int w    = (blockIdx.x * blockDim.x + threadIdx.x) >> 5;
    int lane = threadIdx.x & 31;
    if (w >= n * H) return;
    int h = w & 3;
    float4 v  = *(const float4*)(g_xh + w * C + lane * 4);
    float4 s4 = *(const float4*)(a_src + h * C + lane * 4);
    float4 d4 = *(const float4*)(a_dst + h * C + lane * 4);
    float ss = v.x * s4.x + v.y * s4.y + v.z * s4.z + v.w * s4.w;
    float dd = v.x * d4.x + v.y * d4.y + v.z * d4.z + v.w * d4.w;
#pragma unroll
    for (int o = 16; o; o >>= 1) {
        ss += __shfl_xor_sync(0xffffffffu, ss, o);
        dd += __shfl_xor_sync(0xffffffffu, dd, o);
    }
    if (lane == 0) { g_als[w] = ss; g_ald[w] = dd; }
}

// ---------------- fused edge-softmax + aggregation + mean + bias (+residual) ----------------
__device__ __forceinline__ float lrelu(float x) { return x > 0.f ? x : NEG * x; }

// osel: 0 -> g_h1, 1 -> g_res, 2 -> dout. rsel: 1 -> add g_res.
__global__ void k_agg(const float* __restrict__ bias, float* __restrict__ dout,
                      int n, int osel, int rsel) {
    int node = (blockIdx.x * blockDim.x + threadIdx.x) >> 5;
    int lane = threadIdx.x & 31;
    if (node >= n) return;
    int beg = g_rowptr[node], end = g_rowptr[node + 1];

    float ad0 = g_ald[node * H + 0];
    float ad1 = g_ald[node * H + 1];
    float ad2 = g_ald[node * H + 2];
    float ad3 = g_ald[node * H + 3];

    float m0 = -3.4e38f, m1 = m0, m2 = m0, m3 = m0;
    for (int i = beg + lane; i < end; i += 32) {
        const float* ap = g_als + g_col[i] * H;
        m0 = fmaxf(m0, lrelu(ap[0] + ad0));
        m1 = fmaxf(m1, lrelu(ap[1] + ad1));
        m2 = fmaxf(m2, lrelu(ap[2] + ad2));
        m3 = fmaxf(m3, lrelu(ap[3] + ad3));
    }
#pragma unroll
    for (int o = 16; o; o >>= 1) {
        m0 = fmaxf(m0, __shfl_xor_sync(0xffffffffu, m0, o));
        m1 = fmaxf(m1, __shfl_xor_sync(0xffffffffu, m1, o));
        m2 = fmaxf(m2, __shfl_xor_sync(0xffffffffu, m2, o));
        m3 = fmaxf(m3, __shfl_xor_sync(0xffffffffu, m3, o));
    }

    float d0 = 0.f, d1 = 0.f, d2 = 0.f, d3 = 0.f;
    for (int i = beg + lane; i < end; i += 32) {
        const float* ap = g_als + g_col[i] * H;
        d0 += expf(lrelu(ap[0] + ad0) - m0);
        d1 += expf(lrelu(ap[1] + ad1) - m1);
        d2 += expf(lrelu(ap[2] + ad2) - m2);
        d3 += expf(lrelu(ap[3] + ad3) - m3);
    }
#pragma unroll
    for (int o = 16; o; o >>= 1) {
        d0 += __shfl_xor_sync(0xffffffffu, d0, o);
        d1 += __shfl_xor_sync(0xffffffffu, d1, o);
        d2 += __shfl_xor_sync(0xffffffffu, d2, o);
        d3 += __shfl_xor_sync(0xffffffffu, d3, o);
    }
    float r0 = 1.f / d0, r1 = 1.f / d1, r2 = 1.f / d2, r3 = 1.f / d3;

    float4 acc = make_float4(0.f, 0.f, 0.f, 0.f);
    for (int i = beg; i < end; i++) {
        int s = g_col[i];
        const float* ap = g_als + s * H;
        float w0 = expf(lrelu(ap[0] + ad0) - m0) * r0;
        float w1 = expf(lrelu(ap[1] + ad1) - m1) * r1;
        float w2 = expf(lrelu(ap[2] + ad2) - m2) * r2;
        float w3 = expf(lrelu(ap[3] + ad3) - m3) * r3;
        const float4* xp = (const float4*)(g_xh + s * HC) + lane;
        float4 v0 = xp[0];
        float4 v1 = xp[32];
        float4 v2 = xp[64];
        float4 v3 = xp[96];
        acc.x += w0 * v0.x + w1 * v1.x + w2 * v2.x + w3 * v3.x;
        acc.y += w0 * v0.y + w1 * v1.y + w2 * v2.y + w3 * v3.y;
        acc.z += w0 * v0.z + w1 * v1.z + w2 * v2.z + w3 * v3.z;
        acc.w += w0 * v0.w + w1 * v1.w + w2 * v2.w + w3 * v3.w;
    }

    float4 b4 = *(const float4*)(bias + lane * 4);
    float4 o4;
    o4.x = acc.x * 0.25f + b4.x;
    o4.y = acc.y * 0.25f + b4.y;
    o4.z = acc.z * 0.25f + b4.z;
    o4.w = acc.w * 0.25f + b4.w;
    if (rsel) {
        float4 a4 = *(const float4*)(g_res + node * C + lane * 4);
        o4.x += a4.x; o4.y += a4.y; o4.z += a4.z; o4.w += a4.w;
    }
    float* out = (osel == 0) ? g_h1 : (osel == 1) ? g_res : dout;
    *(float4*)(out + node * C + lane * 4) = o4;
}

// ---------------- host side: kernel launches ONLY ----------------
static void launch_conv(const float* Aext, int asel, const float* W,
                        const float* a_s, const float* a_d, const float* bias,
                        float* dout, int osel, int rsel, int n) {
    dim3 gg((n + BM - 1) / BM, HC / BN);
    k_gemm<<<gg, 256>>>(Aext, W, n, asel);
    k_att<<<(n * H * 32 + 255) / 256, 256>>>(a_s, a_d, n);
    k_agg<<<(n * 32 + 255) / 256, 256>>>(bias, dout, n, osel, rsel);
}

extern "C" void kernel_launch(void* const* d_in, const int* in_sizes, int n_in,
                              void* d_out, int out_size) {
    const float* x   = (const float*)d_in[0];
    const int*   ei  = (const int*)d_in[1];     // int32: JAX x64 disabled
    const float* W1  = (const float*)d_in[2];
    const float* as1 = (const float*)d_in[3];
    const float* ad1 = (const float*)d_in[4];
    const float* b1  = (const float*)d_in[5];
    const float* W2  = (const float*)d_in[6];
    const float* as2 = (const float*)d_in[7];
    const float* ad2 = (const float*)d_in[8];
    const float* b2  = (const float*)d_in[9];
    const float* Wr  = (const float*)d_in[10];
    const float* asr = (const float*)d_in[11];
    const float* adr = (const float*)d_in[12];
    const float* br  = (const float*)d_in[13];

    int n = in_sizes[0] / C;   // 20000
    int e = in_sizes[1] / 2;   // 320000

    // CSR (by dst) build — reused by all three convs
    k_zero_cnt<<<(n + 255) / 256, 256>>>(n);
    k_hist<<<(e + n + 255) / 256, 256>>>(ei, e, n);
    k_scan<<<1, 1024>>>(n);
    k_scatter<<<(e + n + 255) / 256, 256>>>(ei, e, n);

    // h1 = GAT1(x); res = GATr(x); out = GAT2(h1) + res
    launch_conv(x,       0, W1, as1, ad1, b1, nullptr,        0, 0, n);
    launch_conv(x,       0, Wr, asr, adr, br, nullptr,        1, 0, n);
    launch_conv(nullptr, 1, W2, as2, ad2, b2, (float*)d_out,  2, 1, n);
}

// round 9
// speedup vs baseline: 1.1339x; 1.1339x over previous
#include <cuda_runtime.h>
#include <cuda_fp16.h>
#include <stdint.h>

#define NN 20000
#define NE 320000
#define NT (NN + NE)
#define C  128
#define H  4
#define HC 512
#define BM 64
#define BN 64
#define BK 64
#define NEG 0.2f

// ---------------- device scratch (static, no allocation) ----------------
__device__ __align__(16) float  g_xh[NN * HC];    // fp32 features (exact logits)
__device__ __align__(16) __half g_xhh[NN * HC];   // fp16 mirror (gather traffic)
__device__ __align__(16) float  g_h1[NN * C];
__device__ __align__(16) float  g_res[NN * C];
__device__ __align__(16) float  g_als[NN * H];
__device__ __align__(16) float  g_ald[NN * H];
__device__ __align__(16) float4 g_alpha[NT];      // per-edge softmax numerators
__device__ int g_rowptr[NN + 1];
__device__ int g_cnt[NN];
__device__ int g_wp[NN];
__device__ int g_col[NT];

// ---------------- CSR build (int32 edge_index; JAX x64 disabled) ----------------
__global__ void k_zero_cnt(int n) {
    int i = blockIdx.x * blockDim.x + threadIdx.x;
    if (i < n) g_cnt[i] = 0;
}
__global__ void k_hist(const int* __restrict__ ei, int e, int n) {
    int i = blockIdx.x * blockDim.x + threadIdx.x;
    if (i >= e + n) return;
    int d = (i < e) ? ei[e + i] : (i - e);
    if ((unsigned)d < (unsigned)n) atomicAdd(&g_cnt[d], 1);
}
__global__ void k_scan(int n) {
    __shared__ int s[1024];
    __shared__ int carry;
    int tid = threadIdx.x;
    if (tid == 0) carry = 0;
    __syncthreads();
    for (int base = 0; base < n; base += 1024) {
        int i = base + tid;
        int v = (i < n) ? g_cnt[i] : 0;
        s[tid] = v;
        __syncthreads();
        for (int off = 1; off < 1024; off <<= 1) {
            int t = (tid >= off) ? s[tid - off] : 0;
            __syncthreads();
            s[tid] += t;
            __syncthreads();
        }
        int excl = s[tid] - v + carry;
        if (i < n) { g_rowptr[i] = excl; g_wp[i] = excl; }
        __syncthreads();
        if (tid == 1023) carry += s[1023];
        __syncthreads();
    }
    if (tid == 0) g_rowptr[n] = carry;
}
__global__ void k_scatter(const int* __restrict__ ei, int e, int n) {
    int i = blockIdx.x * blockDim.x + threadIdx.x;
    if (i >= e + n) return;
    int s, d;
    if (i < e) { s = ei[i]; d = ei[e + i]; }
    else       { s = i - e; d = s; }
    if ((unsigned)d >= (unsigned)n || (unsigned)s >= (unsigned)n) return;
    int pos = atomicAdd(&g_wp[d], 1);
    g_col[pos] = s;
}

// ---------------- SGEMM (proven round-7): g_xh / g_xhh = A @ W[head] ----------------
__global__ void __launch_bounds__(256) k_gemm(const float* __restrict__ Aext,
                                              const float* __restrict__ W,
                                              int M, int asel) {
    __shared__ float As[BM][BK + 4];
    __shared__ float Bs[BK][BN];
    const float* A = asel ? (const float*)g_h1 : Aext;

    int tid = threadIdx.x;
    int m0 = blockIdx.x * BM;
    int n0 = blockIdx.y * BN;
    const float* Wb = W + (n0 >> 7) * (C * C) + (n0 & 127);

    int tx = tid & 15;
    int ty = tid >> 4;
    float acc[4][4] = {};

    for (int kk = 0; kk < C; kk += BK) {
#pragma unroll
        for (int it = 0; it < 4; it++) {
            int q   = tid + it * 256;
            int row = q >> 4;
            int kc  = (q & 15) << 2;
            float4 v = make_float4(0.f, 0.f, 0.f, 0.f);
            if (m0 + row < M) v = *(const float4*)(A + (size_t)(m0 + row) * C + kk + kc);
            *(float4*)(&As[row][kc]) = v;
        }
#pragma unroll
        for (int it = 0; it < 4; it++) {
            int q  = tid + it * 256;
            int k  = q >> 4;
            int nc = (q & 15) << 2;
            *(float4*)(&Bs[k][nc]) = *(const float4*)(Wb + (size_t)(kk + k) * C + nc);
        }
        __syncthreads();

#pragma unroll 8
        for (int k = 0; k < BK; k++) {
            float4 b = *(const float4*)(&Bs[k][tx * 4]);
            float a0 = As[ty * 4 + 0][k];
            float a1 = As[ty * 4 + 1][k];
            float a2 = As[ty * 4 + 2][k];
            float a3 = As[ty * 4 + 3][k];
            acc[0][0] += a0 * b.x; acc[0][1] += a0 * b.y; acc[0][2] += a0 * b.z; acc[0][3] += a0 * b.w;
            acc[1][0] += a1 * b.x; acc[1][1] += a1 * b.y; acc[1][2] += a1 * b.z; acc[1][3] += a1 * b.w;
            acc[2][0] += a2 * b.x; acc[2][1] += a2 * b.y; acc[2][2] += a2 * b.z; acc[2][3] += a2 * b.w;
            acc[3][0] += a3 * b.x; acc[3][1] += a3 * b.y; acc[3][2] += a3 * b.z; acc[3][3] += a3 * b.w;
        }
        __syncthreads();
    }

#pragma unroll
    for (int i = 0; i < 4; i++) {
        int mrow = m0 + ty * 4 + i;
        if (mrow < M) {
            float4 o = make_float4(acc[i][0], acc[i][1], acc[i][2], acc[i][3]);
            size_t off = (size_t)mrow * HC + n0 + tx * 4;
            *(float4*)(g_xh + off) = o;
            __half2 h0 = __floats2half2_rn(o.x, o.y);
            __half2 h1 = __floats2half2_rn(o.z, o.w);
            uint2 pk = make_uint2(*(uint32_t*)&h0, *(uint32_t*)&h1);
            *(uint2*)(g_xhh + off) = pk;
        }
    }
}

// ---------------- attention logits (exact, fp32 features) ----------------
__global__ void k_att(const float* __restrict__ a_src, const float* __restrict__ a_dst, int n) {
    int w    = (blockIdx.x * blockDim.x + threadIdx.x) >> 5;
    int lane = threadIdx.x & 31;
    if (w >= n * H) return;
    int h = w & 3;
    float4 v  = *(const float4*)(g_xh + (size_t)w * C + lane * 4);
    float4 s4 = *(const float4*)(a_src + h * C + lane * 4);
    float4 d4 = *(const float4*)(a_dst + h * C + lane * 4);
    float ss = v.x * s4.x + v.y * s4.y + v.z * s4.z + v.w * s4.w;
    float dd = v.x * d4.x + v.y * d4.y + v.z * d4.z + v.w * d4.w;
#pragma unroll
    for (int o = 16; o; o >>= 1) {
        ss += __shfl_xor_sync(0xffffffffu, ss, o);
        dd += __shfl_xor_sync(0xffffffffu, dd, o);
    }
    if (lane == 0) { g_als[w] = ss; g_ald[w] = dd; }
}

// ---------------- fused edge-softmax + aggregation ----------------
__device__ __forceinline__ float lrelu(float x) { return x > 0.f ? x : NEG * x; }

// osel: 0 -> g_h1, 1 -> g_res, 2 -> dout. rsel: 1 -> add g_res.
__global__ void k_agg(const float* __restrict__ bias, float* __restrict__ dout,
                      int n, int osel, int rsel) {
    int node = (blockIdx.x * blockDim.x + threadIdx.x) >> 5;
    int lane = threadIdx.x & 31;
    if (node >= n) return;
    int beg = g_rowptr[node], end = g_rowptr[node + 1];

    float ad0 = g_ald[node * H + 0];
    float ad1 = g_ald[node * H + 1];
    float ad2 = g_ald[node * H + 2];
    float ad3 = g_ald[node * H + 3];

    // pass 1: per-head max (lane-parallel)
    float m0 = -3.4e38f, m1 = m0, m2 = m0, m3 = m0;
    for (int i = beg + lane; i < end; i += 32) {
        const float* ap = g_als + g_col[i] * H;
        m0 = fmaxf(m0, lrelu(ap[0] + ad0));
        m1 = fmaxf(m1, lrelu(ap[1] + ad1));
        m2 = fmaxf(m2, lrelu(ap[2] + ad2));
        m3 = fmaxf(m3, lrelu(ap[3] + ad3));
    }
#pragma unroll
    for (int o = 16; o; o >>= 1) {
        m0 = fmaxf(m0, __shfl_xor_sync(0xffffffffu, m0, o));
        m1 = fmaxf(m1, __shfl_xor_sync(0xffffffffu, m1, o));
        m2 = fmaxf(m2, __shfl_xor_sync(0xffffffffu, m2, o));
        m3 = fmaxf(m3, __shfl_xor_sync(0xffffffffu, m3, o));
    }

    // pass 2: numerators -> g_alpha (lane-parallel), accumulate denominators
    float d0 = 0.f, d1 = 0.f, d2 = 0.f, d3 = 0.f;
    for (int i = beg + lane; i < end; i += 32) {
        const float* ap = g_als + g_col[i] * H;
        float e0 = expf(lrelu(ap[0] + ad0) - m0);
        float e1 = expf(lrelu(ap[1] + ad1) - m1);
        float e2 = expf(lrelu(ap[2] + ad2) - m2);
        float e3 = expf(lrelu(ap[3] + ad3) - m3);
        g_alpha[i] = make_float4(e0, e1, e2, e3);
        d0 += e0; d1 += e1; d2 += e2; d3 += e3;
    }
#pragma unroll
    for (int o = 16; o; o >>= 1) {
        d0 += __shfl_xor_sync(0xffffffffu, d0, o);
        d1 += __shfl_xor_sync(0xffffffffu, d1, o);
        d2 += __shfl_xor_sync(0xffffffffu, d2, o);
        d3 += __shfl_xor_sync(0xffffffffu, d3, o);
    }
    float r0 = 1.f / d0, r1 = 1.f / d1, r2 = 1.f / d2, r3 = 1.f / d3;

    // pass 3: weighted gather of fp16 features (whole warp per edge, 1KB/edge)
    float4 acc = make_float4(0.f, 0.f, 0.f, 0.f);
    for (int i = beg; i < end; i++) {
        int s = g_col[i];
        float4 w4 = g_alpha[i];                       // broadcast read
        float w0 = w4.x * r0, w1 = w4.y * r1, w2 = w4.z * r2, w3 = w4.w * r3;
        const __half* xb = g_xhh + (size_t)s * HC;
        uint2 q0 = *(const uint2*)(xb + 0 * C + lane * 4);
        uint2 q1 = *(const uint2*)(xb + 1 * C + lane * 4);
        uint2 q2 = *(const uint2*)(xb + 2 * C + lane * 4);
        uint2 q3 = *(const uint2*)(xb + 3 * C + lane * 4);
        float2 a0 = __half22float2(*(__half2*)&q0.x), b0 = __half22float2(*(__half2*)&q0.y);
        float2 a1 = __half22float2(*(__half2*)&q1.x), b1 = __half22float2(*(__half2*)&q1.y);
        float2 a2 = __half22float2(*(__half2*)&q2.x), b2 = __half22float2(*(__half2*)&q2.y);
        float2 a3 = __half22float2(*(__half2*)&q3.x), b3 = __half22float2(*(__half2*)&q3.y);
        acc.x += w0 * a0.x + w1 * a1.x + w2 * a2.x + w3 * a3.x;
        acc.y += w0 * a0.y + w1 * a1.y + w2 * a2.y + w3 * a3.y;
        acc.z += w0 * b0.x + w1 * b1.x + w2 * b2.x + w3 * b3.x;
        acc.w += w0 * b0.y + w1 * b1.y + w2 * b2.y + w3 * b3.y;
    }

    float4 b4 = *(const float4*)(bias + lane * 4);
    float4 o4;
    o4.x = acc.x * 0.25f + b4.x;
    o4.y = acc.y * 0.25f + b4.y;
    o4.z = acc.z * 0.25f + b4.z;
    o4.w = acc.w * 0.25f + b4.w;
    if (rsel) {
        float4 a4 = *(const float4*)(g_res + (size_t)node * C + lane * 4);
        o4.x += a4.x; o4.y += a4.y; o4.z += a4.z; o4.w += a4.w;
    }
    float* out = (osel == 0) ? g_h1 : (osel == 1) ? g_res : dout;
    *(float4*)(out + (size_t)node * C + lane * 4) = o4;
}

// ---------------- host side ----------------
static void launch_conv(const float* Aext, int asel, const float* W,
                        const float* a_s, const float* a_d, const float* bias,
                        float* dout, int osel, int rsel, int n) {
    dim3 gg((n + BM - 1) / BM, HC / BN);
    k_gemm<<<gg, 256>>>(Aext, W, n, asel);
    k_att<<<(n * H * 32 + 255) / 256, 256>>>(a_s, a_d, n);
    k_agg<<<(n * 32 + 255) / 256, 256>>>(bias, dout, n, osel, rsel);
}

extern "C" void kernel_launch(void* const* d_in, const int* in_sizes, int n_in,
                              void* d_out, int out_size) {
    const float* x   = (const float*)d_in[0];
    const int*   ei  = (const int*)d_in[1];     // int32 (JAX x64 disabled)
    const float* W1  = (const float*)d_in[2];
    const float* as1 = (const float*)d_in[3];
    const float* ad1 = (const float*)d_in[4];
    const float* b1  = (const float*)d_in[5];
    const float* W2  = (const float*)d_in[6];
    const float* as2 = (const float*)d_in[7];
    const float* ad2 = (const float*)d_in[8];
    const float* b2  = (const float*)d_in[9];
    const float* Wr  = (const float*)d_in[10];
    const float* asr = (const float*)d_in[11];
    const float* adr = (const float*)d_in[12];
    const float* br  = (const float*)d_in[13];

    int n = in_sizes[0] / C;
    int e = in_sizes[1] / 2;

    k_zero_cnt<<<(n + 255) / 256, 256>>>(n);
    k_hist<<<(e + n + 255) / 256, 256>>>(ei, e, n);
    k_scan<<<1, 1024>>>(n);
    k_scatter<<<(e + n + 255) / 256, 256>>>(ei, e, n);

    launch_conv(x,       0, W1, as1, ad1, b1, nullptr,       0, 0, n);
    launch_conv(x,       0, Wr, asr, adr, br, nullptr,       1, 0, n);
    launch_conv(nullptr, 1, W2, as2, ad2, b2, (float*)d_out, 2, 1, n);
}

// round 10
// speedup vs baseline: 1.2098x; 1.0669x over previous
#include <cuda_runtime.h>
#include <cuda_fp16.h>
#include <stdint.h>

#define NN 20000
#define NE 320000
#define NT (NN + NE)
#define C  128
#define H  4
#define HC 512
#define NEG 0.2f

#define GBM 128              // GEMM CTA tile rows
#define KH  64               // K half staged in smem
#define LDA 68               // padded leading dims (stride % 32 == 4 -> conflict-free)
#define LDB 68
#define SMEM_GEMM ((GBM * LDA + C * LDB) * 4)   // 69,632 B dynamic

// ---------------- device scratch (static, no allocation) ----------------
__device__ __align__(16) float  g_xh[NN * HC];    // fp32 features (exact logits)
__device__ __align__(16) __half g_xhh[NN * HC];   // fp16 mirror (gather traffic)
__device__ __align__(16) float  g_h1[NN * C];
__device__ __align__(16) float  g_res[NN * C];
__device__ __align__(16) float  g_als[NN * H];
__device__ __align__(16) float  g_ald[NN * H];
__device__ __align__(16) float4 g_alpha[NT];
__device__ int g_rowptr[NN + 1];
__device__ int g_cnt[NN];
__device__ int g_wp[NN];
__device__ int g_col[NT];

// ---------------- CSR build (int32 edge_index; JAX x64 disabled) ----------------
__global__ void k_zero_cnt(int n) {
    int i = blockIdx.x * blockDim.x + threadIdx.x;
    if (i < n) g_cnt[i] = 0;
}
__global__ void k_hist(const int* __restrict__ ei, int e, int n) {
    int i = blockIdx.x * blockDim.x + threadIdx.x;
    if (i >= e + n) return;
    int d = (i < e) ? ei[e + i] : (i - e);
    if ((unsigned)d < (unsigned)n) atomicAdd(&g_cnt[d], 1);
}
__global__ void k_scan(int n) {
    __shared__ int s[1024];
    __shared__ int carry;
    int tid = threadIdx.x;
    if (tid == 0) carry = 0;
    __syncthreads();
    for (int base = 0; base < n; base += 1024) {
        int i = base + tid;
        int v = (i < n) ? g_cnt[i] : 0;
        s[tid] = v;
        __syncthreads();
        for (int off = 1; off < 1024; off <<= 1) {
            int t = (tid >= off) ? s[tid - off] : 0;
            __syncthreads();
            s[tid] += t;
            __syncthreads();
        }
        int excl = s[tid] - v + carry;
        if (i < n) { g_rowptr[i] = excl; g_wp[i] = excl; }
        __syncthreads();
        if (tid == 1023) carry += s[1023];
        __syncthreads();
    }
    if (tid == 0) g_rowptr[n] = carry;
}
__global__ void k_scatter(const int* __restrict__ ei, int e, int n) {
    int i = blockIdx.x * blockDim.x + threadIdx.x;
    if (i >= e + n) return;
    int s, d;
    if (i < e) { s = ei[i]; d = ei[e + i]; }
    else       { s = i - e; d = s; }
    if ((unsigned)d >= (unsigned)n || (unsigned)s >= (unsigned)n) return;
    int pos = atomicAdd(&g_wp[d], 1);
    g_col[pos] = s;
}

// ---------------- tf32 mma.sync GEMM (3-way split = fp32-grade) ----------------
__device__ __forceinline__ void mma8(float& c0, float& c1, float& c2, float& c3,
                                     uint32_t a0, uint32_t a1, uint32_t a2, uint32_t a3,
                                     uint32_t b0, uint32_t b1) {
    asm volatile(
        "mma.sync.aligned.m16n8k8.row.col.f32.tf32.tf32.f32 "
        "{%0,%1,%2,%3}, {%4,%5,%6,%7}, {%8,%9}, {%0,%1,%2,%3};"
        : "+f"(c0), "+f"(c1), "+f"(c2), "+f"(c3)
        : "r"(a0), "r"(a1), "r"(a2), "r"(a3), "r"(b0), "r"(b1));
}
__device__ __forceinline__ uint32_t hi_mask(uint32_t u) { return u & 0xffffe000u; }

// g_xh[m, head*128+o] (fp32) and g_xhh (fp16) = A[m,:] @ W[head]
__global__ void __launch_bounds__(256) k_gemm_mma(const float* __restrict__ Aext,
                                                  const float* __restrict__ W,
                                                  int M, int asel) {
    extern __shared__ float sm[];
    float* As = sm;                 // [GBM][LDA], cols = current K half
    float* Bs = sm + GBM * LDA;     // [C n][LDB k], transposed W

    const float* A = asel ? (const float*)g_h1 : Aext;
    int tid  = threadIdx.x;
    int wid  = tid >> 5, lane = tid & 31;
    int g    = lane >> 2, tig = lane & 3;
    int wm   = wid >> 1;            // 0..3 -> 32-row band
    int wn   = wid & 1;             // 0..1 -> 64-col band
    int m0   = blockIdx.x * GBM;
    int head = blockIdx.y;
    const float* Wb = W + head * (C * C);

    float acc[2][8][4];
#pragma unroll
    for (int mi = 0; mi < 2; mi++)
#pragma unroll
        for (int ni = 0; ni < 8; ni++)
#pragma unroll
            for (int j = 0; j < 4; j++) acc[mi][ni][j] = 0.f;

    for (int half = 0; half < 2; half++) {
        int kbase = half * KH;
        // stage A: 128 rows x 64 cols (fp32), coalesced float4
#pragma unroll
        for (int it = 0; it < 8; it++) {
            int q   = tid + it * 256;          // 0..2047
            int row = q >> 4;
            int c4  = (q & 15) << 2;
            float4 v = make_float4(0.f, 0.f, 0.f, 0.f);
            if (m0 + row < M) v = *(const float4*)(A + (size_t)(m0 + row) * C + kbase + c4);
            *(float4*)(&As[row * LDA + c4]) = v;
        }
        // stage B transposed: Bs[n][k] = W[kbase+k][n], 4x4 float4 transpose blocks
#pragma unroll
        for (int it = 0; it < 2; it++) {
            int q  = tid + it * 256;           // 0..511
            int kb = (q & 15) << 2;            // k block 0..60
            int nb = (q >> 4) << 2;            // n block 0..124
            float4 r0 = *(const float4*)(Wb + (size_t)(kbase + kb + 0) * C + nb);
            float4 r1 = *(const float4*)(Wb + (size_t)(kbase + kb + 1) * C + nb);
            float4 r2 = *(const float4*)(Wb + (size_t)(kbase + kb + 2) * C + nb);
            float4 r3 = *(const float4*)(Wb + (size_t)(kbase + kb + 3) * C + nb);
            *(float4*)(&Bs[(nb + 0) * LDB + kb]) = make_float4(r0.x, r1.x, r2.x, r3.x);
            *(float4*)(&Bs[(nb + 1) * LDB + kb]) = make_float4(r0.y, r1.y, r2.y, r3.y);
            *(float4*)(&Bs[(nb + 2) * LDB + kb]) = make_float4(r0.z, r1.z, r2.z, r3.z);
            *(float4*)(&Bs[(nb + 3) * LDB + kb]) = make_float4(r0.w, r1.w, r2.w, r3.w);
        }
        __syncthreads();

#pragma unroll
        for (int kc = 0; kc < 8; kc++) {
            int k0 = kc * 8 + tig, k1 = k0 + 4;
            // A fragments (hi/lo)
            uint32_t ah[2][4], al[2][4];
#pragma unroll
            for (int mi = 0; mi < 2; mi++) {
                int r0 = wm * 32 + mi * 16 + g, r1 = r0 + 8;
                uint32_t f0 = __float_as_uint(As[r0 * LDA + k0]);
                uint32_t f1 = __float_as_uint(As[r1 * LDA + k0]);
                uint32_t f2 = __float_as_uint(As[r0 * LDA + k1]);
                uint32_t f3 = __float_as_uint(As[r1 * LDA + k1]);
                ah[mi][0] = hi_mask(f0); al[mi][0] = __float_as_uint(__uint_as_float(f0) - __uint_as_float(ah[mi][0]));
                ah[mi][1] = hi_mask(f1); al[mi][1] = __float_as_uint(__uint_as_float(f1) - __uint_as_float(ah[mi][1]));
                ah[mi][2] = hi_mask(f2); al[mi][2] = __float_as_uint(__uint_as_float(f2) - __uint_as_float(ah[mi][2]));
                ah[mi][3] = hi_mask(f3); al[mi][3] = __float_as_uint(__uint_as_float(f3) - __uint_as_float(ah[mi][3]));
            }
            // B fragments (hi/lo)
            uint32_t bh[8][2], bl[8][2];
#pragma unroll
            for (int ni = 0; ni < 8; ni++) {
                int n = wn * 64 + ni * 8 + g;
                uint32_t f0 = __float_as_uint(Bs[n * LDB + k0]);
                uint32_t f1 = __float_as_uint(Bs[n * LDB + k1]);
                bh[ni][0] = hi_mask(f0); bl[ni][0] = __float_as_uint(__uint_as_float(f0) - __uint_as_float(bh[ni][0]));
                bh[ni][1] = hi_mask(f1); bl[ni][1] = __float_as_uint(__uint_as_float(f1) - __uint_as_float(bh[ni][1]));
            }
#pragma unroll
            for (int mi = 0; mi < 2; mi++)
#pragma unroll
                for (int ni = 0; ni < 8; ni++) {
                    float* c = acc[mi][ni];
                    mma8(c[0], c[1], c[2], c[3], ah[mi][0], ah[mi][1], ah[mi][2], ah[mi][3], bh[ni][0], bh[ni][1]);
                    mma8(c[0], c[1], c[2], c[3], al[mi][0], al[mi][1], al[mi][2], al[mi][3], bh[ni][0], bh[ni][1]);
                    mma8(c[0], c[1], c[2], c[3], ah[mi][0], ah[mi][1], ah[mi][2], ah[mi][3], bl[ni][0], bl[ni][1]);
                }
        }
        __syncthreads();
    }

    // epilogue: acc -> g_xh (fp32) + g_xhh (fp16)
#pragma unroll
    for (int mi = 0; mi < 2; mi++) {
#pragma unroll
        for (int ni = 0; ni < 8; ni++) {
            int col = wn * 64 + ni * 8 + 2 * tig;
            int r0  = m0 + wm * 32 + mi * 16 + g;
            int r1  = r0 + 8;
            float* c = acc[mi][ni];
            if (r0 < M) {
                size_t off = (size_t)r0 * HC + head * C + col;
                *(float2*)(g_xh + off) = make_float2(c[0], c[1]);
                __half2 h = __floats2half2_rn(c[0], c[1]);
                *(uint32_t*)(g_xhh + off) = *(uint32_t*)&h;
            }
            if (r1 < M) {
                size_t off = (size_t)r1 * HC + head * C + col;
                *(float2*)(g_xh + off) = make_float2(c[2], c[3]);
                __half2 h = __floats2half2_rn(c[2], c[3]);
                *(uint32_t*)(g_xhh + off) = *(uint32_t*)&h;
            }
        }
    }
}

// ---------------- attention logits (exact, fp32 features) ----------------
__global__ void k_att(const float* __restrict__ a_src, const float* __restrict__ a_dst, int n) {
    int w    = (blockIdx.x * blockDim.x + threadIdx.x) >> 5;
    int lane = threadIdx.x & 31;
    if (w >= n * H) return;
    int h = w & 3;
    float4 v  = *(const float4*)(g_xh + (size_t)w * C + lane * 4);
    float4 s4 = *(const float4*)(a_src + h * C + lane * 4);
    float4 d4 = *(const float4*)(a_dst + h * C + lane * 4);
    float ss = v.x * s4.x + v.y * s4.y + v.z * s4.z + v.w * s4.w;
    float dd = v.x * d4.x + v.y * d4.y + v.z * d4.z + v.w * d4.w;
#pragma unroll
    for (int o = 16; o; o >>= 1) {
        ss += __shfl_xor_sync(0xffffffffu, ss, o);
        dd += __shfl_xor_sync(0xffffffffu, dd, o);
    }
    if (lane == 0) { g_als[w] = ss; g_ald[w] = dd; }
}

// ---------------- fused edge-softmax + aggregation ----------------
__device__ __forceinline__ float lrelu(float x) { return x > 0.f ? x : NEG * x; }

__global__ void k_agg(const float* __restrict__ bias, float* __restrict__ dout,
                      int n, int osel, int rsel) {
    int node = (blockIdx.x * blockDim.x + threadIdx.x) >> 5;
    int lane = threadIdx.x & 31;
    if (node >= n) return;
    int beg = g_rowptr[node], end = g_rowptr[node + 1];

    float ad0 = g_ald[node * H + 0];
    float ad1 = g_ald[node * H + 1];
    float ad2 = g_ald[node * H + 2];
    float ad3 = g_ald[node * H + 3];

    float m0 = -3.4e38f, m1 = m0, m2 = m0, m3 = m0;
    for (int i = beg + lane; i < end; i += 32) {
        const float* ap = g_als + g_col[i] * H;
        m0 = fmaxf(m0, lrelu(ap[0] + ad0));
        m1 = fmaxf(m1, lrelu(ap[1] + ad1));
        m2 = fmaxf(m2, lrelu(ap[2] + ad2));
        m3 = fmaxf(m3, lrelu(ap[3] + ad3));
    }
#pragma unroll
    for (int o = 16; o; o >>= 1) {
        m0 = fmaxf(m0, __shfl_xor_sync(0xffffffffu, m0, o));
        m1 = fmaxf(m1, __shfl_xor_sync(0xffffffffu, m1, o));
        m2 = fmaxf(m2, __shfl_xor_sync(0xffffffffu, m2, o));
        m3 = fmaxf(m3, __shfl_xor_sync(0xffffffffu, m3, o));
    }

    float d0 = 0.f, d1 = 0.f, d2 = 0.f, d3 = 0.f;
    for (int i = beg + lane; i < end; i += 32) {
        const float* ap = g_als + g_col[i] * H;
        float e0 = expf(lrelu(ap[0] + ad0) - m0);
        float e1 = expf(lrelu(ap[1] + ad1) - m1);
        float e2 = expf(lrelu(ap[2] + ad2) - m2);
        float e3 = expf(lrelu(ap[3] + ad3) - m3);
        g_alpha[i] = make_float4(e0, e1, e2, e3);
        d0 += e0; d1 += e1; d2 += e2; d3 += e3;
    }
#pragma unroll
    for (int o = 16; o; o >>= 1) {
        d0 += __shfl_xor_sync(0xffffffffu, d0, o);
        d1 += __shfl_xor_sync(0xffffffffu, d1, o);
        d2 += __shfl_xor_sync(0xffffffffu, d2, o);
        d3 += __shfl_xor_sync(0xffffffffu, d3, o);
    }
    float r0 = 1.f / d0, r1 = 1.f / d1, r2 = 1.f / d2, r3 = 1.f / d3;

    float4 acc = make_float4(0.f, 0.f, 0.f, 0.f);
    for (int i = beg; i < end; i++) {
        int s = g_col[i];
        float4 w4 = g_alpha[i];
        float w0 = w4.x * r0, w1 = w4.y * r1, w2 = w4.z * r2, w3 = w4.w * r3;
        const __half* xb = g_xhh + (size_t)s * HC;
        uint2 q0 = *(const uint2*)(xb + 0 * C + lane * 4);
        uint2 q1 = *(const uint2*)(xb + 1 * C + lane * 4);
        uint2 q2 = *(const uint2*)(xb + 2 * C + lane * 4);
        uint2 q3 = *(const uint2*)(xb + 3 * C + lane * 4);
        float2 a0 = __half22float2(*(__half2*)&q0.x), b0 = __half22float2(*(__half2*)&q0.y);
        float2 a1 = __half22float2(*(__half2*)&q1.x), b1 = __half22float2(*(__half2*)&q1.y);
        float2 a2 = __half22float2(*(__half2*)&q2.x), b2 = __half22float2(*(__half2*)&q2.y);
        float2 a3 = __half22float2(*(__half2*)&q3.x), b3 = __half22float2(*(__half2*)&q3.y);
        acc.x += w0 * a0.x + w1 * a1.x + w2 * a2.x + w3 * a3.x;
        acc.y += w0 * a0.y + w1 * a1.y + w2 * a2.y + w3 * a3.y;
        acc.z += w0 * b0.x + w1 * b1.x + w2 * b2.x + w3 * b3.x;
        acc.w += w0 * b0.y + w1 * b1.y + w2 * b2.y + w3 * b3.y;
    }

    float4 b4 = *(const float4*)(bias + lane * 4);
    float4 o4;
    o4.x = acc.x * 0.25f + b4.x;
    o4.y = acc.y * 0.25f + b4.y;
    o4.z = acc.z * 0.25f + b4.z;
    o4.w = acc.w * 0.25f + b4.w;
    if (rsel) {
        float4 a4 = *(const float4*)(g_res + (size_t)node * C + lane * 4);
        o4.x += a4.x; o4.y += a4.y; o4.z += a4.z; o4.w += a4.w;
    }
    float* out = (osel == 0) ? g_h1 : (osel == 1) ? g_res : dout;
    *(float4*)(out + (size_t)node * C + lane * 4) = o4;
}

// ---------------- host side ----------------
static void launch_conv(const float* Aext, int asel, const float* W,
                        const float* a_s, const float* a_d, const float* bias,
                        float* dout, int osel, int rsel, int n) {
    dim3 gg((n + GBM - 1) / GBM, H);
    k_gemm_mma<<<gg, 256, SMEM_GEMM>>>(Aext, W, n, asel);
    k_att<<<(n * H * 32 + 255) / 256, 256>>>(a_s, a_d, n);
    k_agg<<<(n * 32 + 255) / 256, 256>>>(bias, dout, n, osel, rsel);
}

extern "C" void kernel_launch(void* const* d_in, const int* in_sizes, int n_in,
                              void* d_out, int out_size) {
    const float* x   = (const float*)d_in[0];
    const int*   ei  = (const int*)d_in[1];     // int32 (JAX x64 disabled)
    const float* W1  = (const float*)d_in[2];
    const float* as1 = (const float*)d_in[3];
    const float* ad1 = (const float*)d_in[4];
    const float* b1  = (const float*)d_in[5];
    const float* W2  = (const float*)d_in[6];
    const float* as2 = (const float*)d_in[7];
    const float* ad2 = (const float*)d_in[8];
    const float* b2  = (const float*)d_in[9];
    const float* Wr  = (const float*)d_in[10];
    const float* asr = (const float*)d_in[11];
    const float* adr = (const float*)d_in[12];
    const float* br  = (const float*)d_in[13];

    int n = in_sizes[0] / C;
    int e = in_sizes[1] / 2;

    cudaFuncSetAttribute(k_gemm_mma, cudaFuncAttributeMaxDynamicSharedMemorySize, SMEM_GEMM);

    k_zero_cnt<<<(n + 255) / 256, 256>>>(n);
    k_hist<<<(e + n + 255) / 256, 256>>>(ei, e, n);
    k_scan<<<1, 1024>>>(n);
    k_scatter<<<(e + n + 255) / 256, 256>>>(ei, e, n);

    launch_conv(x,       0, W1, as1, ad1, b1, nullptr,       0, 0, n);
    launch_conv(x,       0, Wr, asr, adr, br, nullptr,       1, 0, n);
    launch_conv(nullptr, 1, W2, as2, ad2, b2, (float*)d_out, 2, 1, n);
}

// round 11
// speedup vs baseline: 1.4871x; 1.2292x over previous
#include <cuda_runtime.h>
#include <cuda_fp16.h>
#include <stdint.h>

#define NN 20000
#define NE 320000
#define NT (NN + NE)
#define C  128
#define H  4
#define HC 512
#define NEG 0.2f

#define GBM 128              // GEMM CTA tile rows
#define KH  64               // K half staged in smem
#define LDA 68               // padded leading dims
#define LDB 68
#define SMEM_GEMM ((GBM * LDA + C * LDB) * 4)   // 69,632 B dynamic

// ---------------- device scratch (static, no allocation) ----------------
__device__ __align__(16) __half g_xhh[NN * HC];   // fp16 features (gather traffic)
__device__ __align__(16) float  g_h1[NN * C];
__device__ __align__(16) float  g_res[NN * C];
__device__ __align__(16) float  g_als[NN * H];
__device__ __align__(16) float  g_ald[NN * H];
__device__ __align__(16) float4 g_alpha[NT];
__device__ int g_rowptr[NN + 1];
__device__ int g_cnt[NN];
__device__ int g_wp[NN];
__device__ int g_col[NT];
__device__ int g_bsum[32];
__device__ int g_boff[32];

// ---------------- CSR build (int32 edge_index; JAX x64 disabled) ----------------
__global__ void k_zero_cnt(int n) {
    int i = blockIdx.x * blockDim.x + threadIdx.x;
    if (i < n) g_cnt[i] = 0;
}
__global__ void k_hist(const int* __restrict__ ei, int e, int n) {
    int i = blockIdx.x * blockDim.x + threadIdx.x;
    if (i >= e + n) return;
    int d = (i < e) ? ei[e + i] : (i - e);
    if ((unsigned)d < (unsigned)n) atomicAdd(&g_cnt[d], 1);
}
// two-level scan: per-block local exclusive scan + block totals
__global__ void k_scan1(int n) {
    __shared__ int s[1024];
    int tid = threadIdx.x;
    int i = blockIdx.x * 1024 + tid;
    int v = (i < n) ? g_cnt[i] : 0;
    s[tid] = v;
    __syncthreads();
#pragma unroll
    for (int off = 1; off < 1024; off <<= 1) {
        int t = (tid >= off) ? s[tid - off] : 0;
        __syncthreads();
        s[tid] += t;
        __syncthreads();
    }
    if (i < n) g_rowptr[i] = s[tid] - v;     // local exclusive
    if (tid == 1023) g_bsum[blockIdx.x] = s[1023];
}
__global__ void k_scan2(int nb, int n) {     // 1 block, 32 threads
    int tid = threadIdx.x;
    int v = (tid < nb) ? g_bsum[tid] : 0;
    int incl = v;
#pragma unroll
    for (int off = 1; off < 32; off <<= 1) {
        int t = __shfl_up_sync(0xffffffffu, incl, off);
        if (tid >= off) incl += t;
    }
    g_boff[tid] = incl - v;                  // exclusive
    if (tid == nb - 1) g_rowptr[n] = incl;   // total
}
__global__ void k_scan3(int n) {
    int i = blockIdx.x * blockDim.x + threadIdx.x;
    if (i >= n) return;
    int v = g_rowptr[i] + g_boff[i >> 10];
    g_rowptr[i] = v;
    g_wp[i] = v;
}
__global__ void k_scatter(const int* __restrict__ ei, int e, int n) {
    int i = blockIdx.x * blockDim.x + threadIdx.x;
    if (i >= e + n) return;
    int s, d;
    if (i < e) { s = ei[i]; d = ei[e + i]; }
    else       { s = i - e; d = s; }
    if ((unsigned)d >= (unsigned)n || (unsigned)s >= (unsigned)n) return;
    int pos = atomicAdd(&g_wp[d], 1);
    g_col[pos] = s;
}

// ---------------- tf32 mma.sync GEMM (3-way split) + fused logits ----------------
__device__ __forceinline__ void mma8(float& c0, float& c1, float& c2, float& c3,
                                     uint32_t a0, uint32_t a1, uint32_t a2, uint32_t a3,
                                     uint32_t b0, uint32_t b1) {
    asm volatile(
        "mma.sync.aligned.m16n8k8.row.col.f32.tf32.tf32.f32 "
        "{%0,%1,%2,%3}, {%4,%5,%6,%7}, {%8,%9}, {%0,%1,%2,%3};"
        : "+f"(c0), "+f"(c1), "+f"(c2), "+f"(c3)
        : "r"(a0), "r"(a1), "r"(a2), "r"(a3), "r"(b0), "r"(b1));
}
__device__ __forceinline__ uint32_t hi_mask(uint32_t u) { return u & 0xffffe000u; }

// g_xhh[m, head*128+o] (fp16) = A[m,:] @ W[head];  g_als/g_ald fused.
__global__ void __launch_bounds__(256) k_gemm_mma(const float* __restrict__ Aext,
                                                  const float* __restrict__ W,
                                                  const float* __restrict__ a_src,
                                                  const float* __restrict__ a_dst,
                                                  int M, int asel) {
    extern __shared__ float sm[];
    float* As = sm;                 // [GBM][LDA]
    float* Bs = sm + GBM * LDA;     // [C n][LDB k]

    const float* A = asel ? (const float*)g_h1 : Aext;
    int tid  = threadIdx.x;
    int wid  = tid >> 5, lane = tid & 31;
    int g    = lane >> 2, tig = lane & 3;
    int wm   = wid >> 1;
    int wn   = wid & 1;
    int m0   = blockIdx.x * GBM;
    int head = blockIdx.y;
    const float* Wb = W + head * (C * C);

    float acc[2][8][4];
#pragma unroll
    for (int mi = 0; mi < 2; mi++)
#pragma unroll
        for (int ni = 0; ni < 8; ni++)
#pragma unroll
            for (int j = 0; j < 4; j++) acc[mi][ni][j] = 0.f;

    for (int half = 0; half < 2; half++) {
        int kbase = half * KH;
#pragma unroll
        for (int it = 0; it < 8; it++) {
            int q   = tid + it * 256;
            int row = q >> 4;
            int c4  = (q & 15) << 2;
            float4 v = make_float4(0.f, 0.f, 0.f, 0.f);
            if (m0 + row < M) v = *(const float4*)(A + (size_t)(m0 + row) * C + kbase + c4);
            *(float4*)(&As[row * LDA + c4]) = v;
        }
#pragma unroll
        for (int it = 0; it < 2; it++) {
            int q  = tid + it * 256;
            int kb = (q & 15) << 2;
            int nb = (q >> 4) << 2;
            float4 r0 = *(const float4*)(Wb + (size_t)(kbase + kb + 0) * C + nb);
            float4 r1 = *(const float4*)(Wb + (size_t)(kbase + kb + 1) * C + nb);
            float4 r2 = *(const float4*)(Wb + (size_t)(kbase + kb + 2) * C + nb);
            float4 r3 = *(const float4*)(Wb + (size_t)(kbase + kb + 3) * C + nb);
            *(float4*)(&Bs[(nb + 0) * LDB + kb]) = make_float4(r0.x, r1.x, r2.x, r3.x);
            *(float4*)(&Bs[(nb + 1) * LDB + kb]) = make_float4(r0.y, r1.y, r2.y, r3.y);
            *(float4*)(&Bs[(nb + 2) * LDB + kb]) = make_float4(r0.z, r1.z, r2.z, r3.z);
            *(float4*)(&Bs[(nb + 3) * LDB + kb]) = make_float4(r0.w, r1.w, r2.w, r3.w);
        }
        __syncthreads();

#pragma unroll
        for (int kc = 0; kc < 8; kc++) {
            int k0 = kc * 8 + tig, k1 = k0 + 4;
            uint32_t ah[2][4], al[2][4];
#pragma unroll
            for (int mi = 0; mi < 2; mi++) {
                int r0 = wm * 32 + mi * 16 + g, r1 = r0 + 8;
                uint32_t f0 = __float_as_uint(As[r0 * LDA + k0]);
                uint32_t f1 = __float_as_uint(As[r1 * LDA + k0]);
                uint32_t f2 = __float_as_uint(As[r0 * LDA + k1]);
                uint32_t f3 = __float_as_uint(As[r1 * LDA + k1]);
                ah[mi][0] = hi_mask(f0); al[mi][0] = __float_as_uint(__uint_as_float(f0) - __uint_as_float(ah[mi][0]));
                ah[mi][1] = hi_mask(f1); al[mi][1] = __float_as_uint(__uint_as_float(f1) - __uint_as_float(ah[mi][1]));
                ah[mi][2] = hi_mask(f2); al[mi][2] = __float_as_uint(__uint_as_float(f2) - __uint_as_float(ah[mi][2]));
                ah[mi][3] = hi_mask(f3); al[mi][3] = __float_as_uint(__uint_as_float(f3) - __uint_as_float(ah[mi][3]));
            }
            uint32_t bh[8][2], bl[8][2];
#pragma unroll
            for (int ni = 0; ni < 8; ni++) {
                int n = wn * 64 + ni * 8 + g;
                uint32_t f0 = __float_as_uint(Bs[n * LDB + k0]);
                uint32_t f1 = __float_as_uint(Bs[n * LDB + k1]);
                bh[ni][0] = hi_mask(f0); bl[ni][0] = __float_as_uint(__uint_as_float(f0) - __uint_as_float(bh[ni][0]));
                bh[ni][1] = hi_mask(f1); bl[ni][1] = __float_as_uint(__uint_as_float(f1) - __uint_as_float(bh[ni][1]));
            }
#pragma unroll
            for (int mi = 0; mi < 2; mi++)
#pragma unroll
                for (int ni = 0; ni < 8; ni++) {
                    float* c = acc[mi][ni];
                    mma8(c[0], c[1], c[2], c[3], ah[mi][0], ah[mi][1], ah[mi][2], ah[mi][3], bh[ni][0], bh[ni][1]);
                    mma8(c[0], c[1], c[2], c[3], al[mi][0], al[mi][1], al[mi][2], al[mi][3], bh[ni][0], bh[ni][1]);
                    mma8(c[0], c[1], c[2], c[3], ah[mi][0], ah[mi][1], ah[mi][2], ah[mi][3], bl[ni][0], bl[ni][1]);
                }
        }
        __syncthreads();
    }

    // ---- epilogue: fp16 store + fused a_src/a_dst logit reduction ----
    float* s_ds = sm;          // [128] per-row src-logit partials
    float* s_dd = sm + 128;    // [128]
    if (tid < 128) { s_ds[tid] = 0.f; s_dd[tid] = 0.f; }
    __syncthreads();

    float ds[4] = {0.f, 0.f, 0.f, 0.f};   // rows wm*32 + {g, g+8, g+16, g+24}
    float dd[4] = {0.f, 0.f, 0.f, 0.f};
#pragma unroll
    for (int mi = 0; mi < 2; mi++) {
#pragma unroll
        for (int ni = 0; ni < 8; ni++) {
            int col = wn * 64 + ni * 8 + 2 * tig;
            float* c = acc[mi][ni];
            float s0 = a_src[head * C + col], s1 = a_src[head * C + col + 1];
            float d0 = a_dst[head * C + col], d1 = a_dst[head * C + col + 1];
            ds[2 * mi + 0] += c[0] * s0 + c[1] * s1;
            ds[2 * mi + 1] += c[2] * s0 + c[3] * s1;
            dd[2 * mi + 0] += c[0] * d0 + c[1] * d1;
            dd[2 * mi + 1] += c[2] * d0 + c[3] * d1;

            int r0 = m0 + wm * 32 + mi * 16 + g;
            if (r0 < M) {
                __half2 h = __floats2half2_rn(c[0], c[1]);
                *(uint32_t*)(g_xhh + (size_t)r0 * HC + head * C + col) = *(uint32_t*)&h;
            }
            if (r0 + 8 < M) {
                __half2 h = __floats2half2_rn(c[2], c[3]);
                *(uint32_t*)(g_xhh + (size_t)(r0 + 8) * HC + head * C + col) = *(uint32_t*)&h;
            }
        }
    }
    // quad-reduce over tig (rows identical across the quad)
#pragma unroll
    for (int j = 0; j < 4; j++) {
#pragma unroll
        for (int o = 1; o < 4; o <<= 1) {
            ds[j] += __shfl_xor_sync(0xffffffffu, ds[j], o);
            dd[j] += __shfl_xor_sync(0xffffffffu, dd[j], o);
        }
    }
    if (tig == 0) {
#pragma unroll
        for (int j = 0; j < 4; j++) {
            int rl = wm * 32 + j * 8 + g;
            atomicAdd(&s_ds[rl], ds[j]);   // 2-way (wn=0/1)
            atomicAdd(&s_dd[rl], dd[j]);
        }
    }
    __syncthreads();
    if (tid < 128 && m0 + tid < M) {
        g_als[(m0 + tid) * H + head] = s_ds[tid];
        g_ald[(m0 + tid) * H + head] = s_dd[tid];
    }
}

// ---------------- fused edge-softmax + aggregation ----------------
__device__ __forceinline__ float lrelu(float x) { return x > 0.f ? x : NEG * x; }

__global__ void k_agg(const float* __restrict__ bias, float* __restrict__ dout,
                      int n, int osel, int rsel) {
    int node = (blockIdx.x * blockDim.x + threadIdx.x) >> 5;
    int lane = threadIdx.x & 31;
    if (node >= n) return;
    int beg = g_rowptr[node], end = g_rowptr[node + 1];

    float ad0 = g_ald[node * H + 0];
    float ad1 = g_ald[node * H + 1];
    float ad2 = g_ald[node * H + 2];
    float ad3 = g_ald[node * H + 3];

    float m0 = -3.4e38f, m1 = m0, m2 = m0, m3 = m0;
    for (int i = beg + lane; i < end; i += 32) {
        const float* ap = g_als + g_col[i] * H;
        m0 = fmaxf(m0, lrelu(ap[0] + ad0));
        m1 = fmaxf(m1, lrelu(ap[1] + ad1));
        m2 = fmaxf(m2, lrelu(ap[2] + ad2));
        m3 = fmaxf(m3, lrelu(ap[3] + ad3));
    }
#pragma unroll
    for (int o = 16; o; o >>= 1) {
        m0 = fmaxf(m0, __shfl_xor_sync(0xffffffffu, m0, o));
        m1 = fmaxf(m1, __shfl_xor_sync(0xffffffffu, m1, o));
        m2 = fmaxf(m2, __shfl_xor_sync(0xffffffffu, m2, o));
        m3 = fmaxf(m3, __shfl_xor_sync(0xffffffffu, m3, o));
    }

    float d0 = 0.f, d1 = 0.f, d2 = 0.f, d3 = 0.f;
    for (int i = beg + lane; i < end; i += 32) {
        const float* ap = g_als + g_col[i] * H;
        float e0 = expf(lrelu(ap[0] + ad0) - m0);
        float e1 = expf(lrelu(ap[1] + ad1) - m1);
        float e2 = expf(lrelu(ap[2] + ad2) - m2);
        float e3 = expf(lrelu(ap[3] + ad3) - m3);
        g_alpha[i] = make_float4(e0, e1, e2, e3);
        d0 += e0; d1 += e1; d2 += e2; d3 += e3;
    }
#pragma unroll
    for (int o = 16; o; o >>= 1) {
        d0 += __shfl_xor_sync(0xffffffffu, d0, o);
        d1 += __shfl_xor_sync(0xffffffffu, d1, o);
        d2 += __shfl_xor_sync(0xffffffffu, d2, o);
        d3 += __shfl_xor_sync(0xffffffffu, d3, o);
    }
    float r0 = 1.f / d0, r1 = 1.f / d1, r2 = 1.f / d2, r3 = 1.f / d3;

    float4 acc = make_float4(0.f, 0.f, 0.f, 0.f);
    for (int i = beg; i < end; i++) {
        int s = g_col[i];
        float4 w4 = g_alpha[i];
        float w0 = w4.x * r0, w1 = w4.y * r1, w2 = w4.z * r2, w3 = w4.w * r3;
        const __half* xb = g_xhh + (size_t)s * HC;
        uint2 q0 = *(const uint2*)(xb + 0 * C + lane * 4);
        uint2 q1 = *(const uint2*)(xb + 1 * C + lane * 4);
        uint2 q2 = *(const uint2*)(xb + 2 * C + lane * 4);
        uint2 q3 = *(const uint2*)(xb + 3 * C + lane * 4);
        float2 a0 = __half22float2(*(__half2*)&q0.x), b0 = __half22float2(*(__half2*)&q0.y);
        float2 a1 = __half22float2(*(__half2*)&q1.x), b1 = __half22float2(*(__half2*)&q1.y);
        float2 a2 = __half22float2(*(__half2*)&q2.x), b2 = __half22float2(*(__half2*)&q2.y);
        float2 a3 = __half22float2(*(__half2*)&q3.x), b3 = __half22float2(*(__half2*)&q3.y);
        acc.x += w0 * a0.x + w1 * a1.x + w2 * a2.x + w3 * a3.x;
        acc.y += w0 * a0.y + w1 * a1.y + w2 * a2.y + w3 * a3.y;
        acc.z += w0 * b0.x + w1 * b1.x + w2 * b2.x + w3 * b3.x;
        acc.w += w0 * b0.y + w1 * b1.y + w2 * b2.y + w3 * b3.y;
    }

    float4 b4 = *(const float4*)(bias + lane * 4);
    float4 o4;
    o4.x = acc.x * 0.25f + b4.x;
    o4.y = acc.y * 0.25f + b4.y;
    o4.z = acc.z * 0.25f + b4.z;
    o4.w = acc.w * 0.25f + b4.w;
    if (rsel) {
        float4 a4 = *(const float4*)(g_res + (size_t)node * C + lane * 4);
        o4.x += a4.x; o4.y += a4.y; o4.z += a4.z; o4.w += a4.w;
    }
    float* out = (osel == 0) ? g_h1 : (osel == 1) ? g_res : dout;
    *(float4*)(out + (size_t)node * C + lane * 4) = o4;
}

// ---------------- host side ----------------
static void launch_conv(const float* Aext, int asel, const float* W,
                        const float* a_s, const float* a_d, const float* bias,
                        float* dout, int osel, int rsel, int n) {
    dim3 gg((n + GBM - 1) / GBM, H);
    k_gemm_mma<<<gg, 256, SMEM_GEMM>>>(Aext, W, a_s, a_d, n, asel);
    k_agg<<<(n * 32 + 255) / 256, 256>>>(bias, dout, n, osel, rsel);
}

extern "C" void kernel_launch(void* const* d_in, const int* in_sizes, int n_in,
                              void* d_out, int out_size) {
    const float* x   = (const float*)d_in[0];
    const int*   ei  = (const int*)d_in[1];     // int32 (JAX x64 disabled)
    const float* W1  = (const float*)d_in[2];
    const float* as1 = (const float*)d_in[3];
    const float* ad1 = (const float*)d_in[4];
    const float* b1  = (const float*)d_in[5];
    const float* W2  = (const float*)d_in[6];
    const float* as2 = (const float*)d_in[7];
    const float* ad2 = (const float*)d_in[8];
    const float* b2  = (const float*)d_in[9];
    const float* Wr  = (const float*)d_in[10];
    const float* asr = (const float*)d_in[11];
    const float* adr = (const float*)d_in[12];
    const float* br  = (const float*)d_in[13];

    int n = in_sizes[0] / C;
    int e = in_sizes[1] / 2;
    int nb = (n + 1023) / 1024;

    cudaFuncSetAttribute(k_gemm_mma, cudaFuncAttributeMaxDynamicSharedMemorySize, SMEM_GEMM);

    k_zero_cnt<<<(n + 255) / 256, 256>>>(n);
    k_hist<<<(e + n + 255) / 256, 256>>>(ei, e, n);
    k_scan1<<<nb, 1024>>>(n);
    k_scan2<<<1, 32>>>(nb, n);
    k_scan3<<<(n + 255) / 256, 256>>>(n);
    k_scatter<<<(e + n + 255) / 256, 256>>>(ei, e, n);

    launch_conv(x,       0, W1, as1, ad1, b1, nullptr,       0, 0, n);
    launch_conv(x,       0, Wr, asr, adr, br, nullptr,       1, 0, n);
    launch_conv(nullptr, 1, W2, as2, ad2, b2, (float*)d_out, 2, 1, n);
}

// round 12
// speedup vs baseline: 1.5540x; 1.0450x over previous
#include <cuda_runtime.h>
#include <cuda_fp16.h>
#include <stdint.h>

#define NN 20000
#define NE 320000
#define NT (NN + NE)
#define C  128
#define H  4
#define HC 512
#define NEG 0.2f

#define GBM 128
#define KH  64
#define LDA 68
#define LDB 68
#define SMEM_GEMM ((GBM * LDA + C * LDB) * 4)   // 69,632 B dynamic

// ---------------- device scratch (static, no allocation) ----------------
__device__ __align__(16) __half g_xhh[NN * HC];    // conv1 / conv2 features (fp16)
__device__ __align__(16) __half g_xhh2[NN * HC];   // conv_r features (fp16)
__device__ __align__(16) float  g_h1[NN * C];
__device__ __align__(16) float  g_res[NN * C];
__device__ __align__(16) float  g_als[NN * H],  g_ald[NN * H];
__device__ __align__(16) float  g_als2[NN * H], g_ald2[NN * H];
__device__ __align__(16) float4 g_alpha[NT];
__device__ __align__(16) float4 g_alpha2[NT];
__device__ int g_rowptr[NN + 1];
__device__ int g_cnt[NN];
__device__ int g_wp[NN];
__device__ int g_col[NT];
__device__ int g_bsum[32];
__device__ int g_boff[32];

// ---------------- CSR build (int32 edge_index; JAX x64 disabled) ----------------
__global__ void k_zero_cnt(int n) {
    int i = blockIdx.x * blockDim.x + threadIdx.x;
    if (i < n) g_cnt[i] = 0;
}
__global__ void k_hist(const int* __restrict__ ei, int e, int n) {
    int i = blockIdx.x * blockDim.x + threadIdx.x;
    if (i >= e + n) return;
    int d = (i < e) ? ei[e + i] : (i - e);
    if ((unsigned)d < (unsigned)n) atomicAdd(&g_cnt[d], 1);
}
__global__ void k_scan1(int n) {
    __shared__ int s[1024];
    int tid = threadIdx.x;
    int i = blockIdx.x * 1024 + tid;
    int v = (i < n) ? g_cnt[i] : 0;
    s[tid] = v;
    __syncthreads();
#pragma unroll
    for (int off = 1; off < 1024; off <<= 1) {
        int t = (tid >= off) ? s[tid - off] : 0;
        __syncthreads();
        s[tid] += t;
        __syncthreads();
    }
    if (i < n) g_rowptr[i] = s[tid] - v;
    if (tid == 1023) g_bsum[blockIdx.x] = s[1023];
}
__global__ void k_scan2(int nb, int n) {
    int tid = threadIdx.x;
    int v = (tid < nb) ? g_bsum[tid] : 0;
    int incl = v;
#pragma unroll
    for (int off = 1; off < 32; off <<= 1) {
        int t = __shfl_up_sync(0xffffffffu, incl, off);
        if (tid >= off) incl += t;
    }
    g_boff[tid] = incl - v;
    if (tid == nb - 1) g_rowptr[n] = incl;
}
__global__ void k_scan3(int n) {
    int i = blockIdx.x * blockDim.x + threadIdx.x;
    if (i >= n) return;
    int v = g_rowptr[i] + g_boff[i >> 10];
    g_rowptr[i] = v;
    g_wp[i] = v;
}
__global__ void k_scatter(const int* __restrict__ ei, int e, int n) {
    int i = blockIdx.x * blockDim.x + threadIdx.x;
    if (i >= e + n) return;
    int s, d;
    if (i < e) { s = ei[i]; d = ei[e + i]; }
    else       { s = i - e; d = s; }
    if ((unsigned)d >= (unsigned)n || (unsigned)s >= (unsigned)n) return;
    int pos = atomicAdd(&g_wp[d], 1);
    g_col[pos] = s;
}

// ---------------- tf32 mma.sync GEMM (3-way split) + fused logits ----------------
__device__ __forceinline__ void mma8(float& c0, float& c1, float& c2, float& c3,
                                     uint32_t a0, uint32_t a1, uint32_t a2, uint32_t a3,
                                     uint32_t b0, uint32_t b1) {
    asm volatile(
        "mma.sync.aligned.m16n8k8.row.col.f32.tf32.tf32.f32 "
        "{%0,%1,%2,%3}, {%4,%5,%6,%7}, {%8,%9}, {%0,%1,%2,%3};"
        : "+f"(c0), "+f"(c1), "+f"(c2), "+f"(c3)
        : "r"(a0), "r"(a1), "r"(a2), "r"(a3), "r"(b0), "r"(b1));
}
__device__ __forceinline__ uint32_t hi_mask(uint32_t u) { return u & 0xffffe000u; }

// blockIdx.y in [0,4): weight-set A -> g_xhh/g_als/g_ald
// blockIdx.y in [4,8): weight-set B -> g_xhh2/g_als2/g_ald2
__global__ void __launch_bounds__(256) k_gemm_mma(const float* __restrict__ Aext,
                                                  const float* __restrict__ Wa,
                                                  const float* __restrict__ asa,
                                                  const float* __restrict__ ada,
                                                  const float* __restrict__ Wbb,
                                                  const float* __restrict__ asb,
                                                  const float* __restrict__ adb,
                                                  int M, int asel) {
    extern __shared__ float sm[];
    float* As = sm;
    float* Bs = sm + GBM * LDA;

    const float* A = asel ? (const float*)g_h1 : Aext;
    int tid  = threadIdx.x;
    int wid  = tid >> 5, lane = tid & 31;
    int g    = lane >> 2, tig = lane & 3;
    int wm   = wid >> 1;
    int wn   = wid & 1;
    int m0   = blockIdx.x * GBM;
    int setb = blockIdx.y >> 2;
    int head = blockIdx.y & 3;

    const float* Wsel = setb ? Wbb : Wa;
    const float* avs  = setb ? asb : asa;
    const float* avd  = setb ? adb : ada;
    __half* xout      = setb ? g_xhh2 : g_xhh;
    float*  alsout    = setb ? g_als2 : g_als;
    float*  aldout    = setb ? g_ald2 : g_ald;
    const float* Wb = Wsel + head * (C * C);

    float acc[2][8][4];
#pragma unroll
    for (int mi = 0; mi < 2; mi++)
#pragma unroll
        for (int ni = 0; ni < 8; ni++)
#pragma unroll
            for (int j = 0; j < 4; j++) acc[mi][ni][j] = 0.f;

    for (int half = 0; half < 2; half++) {
        int kbase = half * KH;
#pragma unroll
        for (int it = 0; it < 8; it++) {
            int q   = tid + it * 256;
            int row = q >> 4;
            int c4  = (q & 15) << 2;
            float4 v = make_float4(0.f, 0.f, 0.f, 0.f);
            if (m0 + row < M) v = *(const float4*)(A + (size_t)(m0 + row) * C + kbase + c4);
            *(float4*)(&As[row * LDA + c4]) = v;
        }
#pragma unroll
        for (int it = 0; it < 2; it++) {
            int q  = tid + it * 256;
            int kb = (q & 15) << 2;
            int nb = (q >> 4) << 2;
            float4 r0 = *(const float4*)(Wb + (size_t)(kbase + kb + 0) * C + nb);
            float4 r1 = *(const float4*)(Wb + (size_t)(kbase + kb + 1) * C + nb);
            float4 r2 = *(const float4*)(Wb + (size_t)(kbase + kb + 2) * C + nb);
            float4 r3 = *(const float4*)(Wb + (size_t)(kbase + kb + 3) * C + nb);
            *(float4*)(&Bs[(nb + 0) * LDB + kb]) = make_float4(r0.x, r1.x, r2.x, r3.x);
            *(float4*)(&Bs[(nb + 1) * LDB + kb]) = make_float4(r0.y, r1.y, r2.y, r3.y);
            *(float4*)(&Bs[(nb + 2) * LDB + kb]) = make_float4(r0.z, r1.z, r2.z, r3.z);
            *(float4*)(&Bs[(nb + 3) * LDB + kb]) = make_float4(r0.w, r1.w, r2.w, r3.w);
        }
        __syncthreads();

#pragma unroll
        for (int kc = 0; kc < 8; kc++) {
            int k0 = kc * 8 + tig, k1 = k0 + 4;
            uint32_t ah[2][4], al[2][4];
#pragma unroll
            for (int mi = 0; mi < 2; mi++) {
                int r0 = wm * 32 + mi * 16 + g, r1 = r0 + 8;
                uint32_t f0 = __float_as_uint(As[r0 * LDA + k0]);
                uint32_t f1 = __float_as_uint(As[r1 * LDA + k0]);
                uint32_t f2 = __float_as_uint(As[r0 * LDA + k1]);
                uint32_t f3 = __float_as_uint(As[r1 * LDA + k1]);
                ah[mi][0] = hi_mask(f0); al[mi][0] = __float_as_uint(__uint_as_float(f0) - __uint_as_float(ah[mi][0]));
                ah[mi][1] = hi_mask(f1); al[mi][1] = __float_as_uint(__uint_as_float(f1) - __uint_as_float(ah[mi][1]));
                ah[mi][2] = hi_mask(f2); al[mi][2] = __float_as_uint(__uint_as_float(f2) - __uint_as_float(ah[mi][2]));
                ah[mi][3] = hi_mask(f3); al[mi][3] = __float_as_uint(__uint_as_float(f3) - __uint_as_float(ah[mi][3]));
            }
            uint32_t bh[8][2], bl[8][2];
#pragma unroll
            for (int ni = 0; ni < 8; ni++) {
                int nn = wn * 64 + ni * 8 + g;
                uint32_t f0 = __float_as_uint(Bs[nn * LDB + k0]);
                uint32_t f1 = __float_as_uint(Bs[nn * LDB + k1]);
                bh[ni][0] = hi_mask(f0); bl[ni][0] = __float_as_uint(__uint_as_float(f0) - __uint_as_float(bh[ni][0]));
                bh[ni][1] = hi_mask(f1); bl[ni][1] = __float_as_uint(__uint_as_float(f1) - __uint_as_float(bh[ni][1]));
            }
#pragma unroll
            for (int mi = 0; mi < 2; mi++)
#pragma unroll
                for (int ni = 0; ni < 8; ni++) {
                    float* c = acc[mi][ni];
                    mma8(c[0], c[1], c[2], c[3], ah[mi][0], ah[mi][1], ah[mi][2], ah[mi][3], bh[ni][0], bh[ni][1]);
                    mma8(c[0], c[1], c[2], c[3], al[mi][0], al[mi][1], al[mi][2], al[mi][3], bh[ni][0], bh[ni][1]);
                    mma8(c[0], c[1], c[2], c[3], ah[mi][0], ah[mi][1], ah[mi][2], ah[mi][3], bl[ni][0], bl[ni][1]);
                }
        }
        __syncthreads();
    }

    // ---- epilogue: fp16 store + fused logit reduction ----
    float* s_ds = sm;
    float* s_dd = sm + 128;
    if (tid < 128) { s_ds[tid] = 0.f; s_dd[tid] = 0.f; }
    __syncthreads();

    float ds[4] = {0.f, 0.f, 0.f, 0.f};
    float dd[4] = {0.f, 0.f, 0.f, 0.f};
#pragma unroll
    for (int mi = 0; mi < 2; mi++) {
#pragma unroll
        for (int ni = 0; ni < 8; ni++) {
            int col = wn * 64 + ni * 8 + 2 * tig;
            float* c = acc[mi][ni];
            float s0 = avs[head * C + col], s1 = avs[head * C + col + 1];
            float d0 = avd[head * C + col], d1 = avd[head * C + col + 1];
            ds[2 * mi + 0] += c[0] * s0 + c[1] * s1;
            ds[2 * mi + 1] += c[2] * s0 + c[3] * s1;
            dd[2 * mi + 0] += c[0] * d0 + c[1] * d1;
            dd[2 * mi + 1] += c[2] * d0 + c[3] * d1;

            int r0 = m0 + wm * 32 + mi * 16 + g;
            if (r0 < M) {
                __half2 h = __floats2half2_rn(c[0], c[1]);
                *(uint32_t*)(xout + (size_t)r0 * HC + head * C + col) = *(uint32_t*)&h;
            }
            if (r0 + 8 < M) {
                __half2 h = __floats2half2_rn(c[2], c[3]);
                *(uint32_t*)(xout + (size_t)(r0 + 8) * HC + head * C + col) = *(uint32_t*)&h;
            }
        }
    }
#pragma unroll
    for (int j = 0; j < 4; j++) {
#pragma unroll
        for (int o = 1; o < 4; o <<= 1) {
            ds[j] += __shfl_xor_sync(0xffffffffu, ds[j], o);
            dd[j] += __shfl_xor_sync(0xffffffffu, dd[j], o);
        }
    }
    if (tig == 0) {
#pragma unroll
        for (int j = 0; j < 4; j++) {
            int rl = wm * 32 + j * 8 + g;
            atomicAdd(&s_ds[rl], ds[j]);
            atomicAdd(&s_dd[rl], dd[j]);
        }
    }
    __syncthreads();
    if (tid < 128 && m0 + tid < M) {
        alsout[(m0 + tid) * H + head] = s_ds[tid];
        aldout[(m0 + tid) * H + head] = s_dd[tid];
    }
}

// ---------------- edge-softmax + aggregation ----------------
__device__ __forceinline__ float lrelu(float x) { return x > 0.f ? x : NEG * x; }
__device__ __forceinline__ float4 f4max(float4 a, float4 b) {
    return make_float4(fmaxf(a.x, b.x), fmaxf(a.y, b.y), fmaxf(a.z, b.z), fmaxf(a.w, b.w));
}

// combined conv1 + conv_r aggregation: writes g_h1 and g_res
__global__ void k_agg2(const float* __restrict__ bias1, const float* __restrict__ biasr, int n) {
    int node = (blockIdx.x * blockDim.x + threadIdx.x) >> 5;
    int lane = threadIdx.x & 31;
    if (node >= n) return;
    int beg = g_rowptr[node], end = g_rowptr[node + 1];

    float4 ad1 = *(const float4*)(g_ald  + node * H);
    float4 ad2 = *(const float4*)(g_ald2 + node * H);

    float4 m1 = make_float4(-3.4e38f, -3.4e38f, -3.4e38f, -3.4e38f), m2 = m1;
    for (int i = beg + lane; i < end; i += 32) {
        int s = g_col[i];
        float4 a1 = *(const float4*)(g_als  + s * H);
        float4 a2 = *(const float4*)(g_als2 + s * H);
        m1 = f4max(m1, make_float4(lrelu(a1.x + ad1.x), lrelu(a1.y + ad1.y), lrelu(a1.z + ad1.z), lrelu(a1.w + ad1.w)));
        m2 = f4max(m2, make_float4(lrelu(a2.x + ad2.x), lrelu(a2.y + ad2.y), lrelu(a2.z + ad2.z), lrelu(a2.w + ad2.w)));
    }
#pragma unroll
    for (int o = 16; o; o >>= 1) {
        m1.x = fmaxf(m1.x, __shfl_xor_sync(0xffffffffu, m1.x, o));
        m1.y = fmaxf(m1.y, __shfl_xor_sync(0xffffffffu, m1.y, o));
        m1.z = fmaxf(m1.z, __shfl_xor_sync(0xffffffffu, m1.z, o));
        m1.w = fmaxf(m1.w, __shfl_xor_sync(0xffffffffu, m1.w, o));
        m2.x = fmaxf(m2.x, __shfl_xor_sync(0xffffffffu, m2.x, o));
        m2.y = fmaxf(m2.y, __shfl_xor_sync(0xffffffffu, m2.y, o));
        m2.z = fmaxf(m2.z, __shfl_xor_sync(0xffffffffu, m2.z, o));
        m2.w = fmaxf(m2.w, __shfl_xor_sync(0xffffffffu, m2.w, o));
    }

    float4 d1 = make_float4(0.f, 0.f, 0.f, 0.f), d2 = d1;
    for (int i = beg + lane; i < end; i += 32) {
        int s = g_col[i];
        float4 a1 = *(const float4*)(g_als  + s * H);
        float4 a2 = *(const float4*)(g_als2 + s * H);
        float4 e1 = make_float4(expf(lrelu(a1.x + ad1.x) - m1.x), expf(lrelu(a1.y + ad1.y) - m1.y),
                                expf(lrelu(a1.z + ad1.z) - m1.z), expf(lrelu(a1.w + ad1.w) - m1.w));
        float4 e2 = make_float4(expf(lrelu(a2.x + ad2.x) - m2.x), expf(lrelu(a2.y + ad2.y) - m2.y),
                                expf(lrelu(a2.z + ad2.z) - m2.z), expf(lrelu(a2.w + ad2.w) - m2.w));
        g_alpha[i] = e1; g_alpha2[i] = e2;
        d1.x += e1.x; d1.y += e1.y; d1.z += e1.z; d1.w += e1.w;
        d2.x += e2.x; d2.y += e2.y; d2.z += e2.z; d2.w += e2.w;
    }
#pragma unroll
    for (int o = 16; o; o >>= 1) {
        d1.x += __shfl_xor_sync(0xffffffffu, d1.x, o);
        d1.y += __shfl_xor_sync(0xffffffffu, d1.y, o);
        d1.z += __shfl_xor_sync(0xffffffffu, d1.z, o);
        d1.w += __shfl_xor_sync(0xffffffffu, d1.w, o);
        d2.x += __shfl_xor_sync(0xffffffffu, d2.x, o);
        d2.y += __shfl_xor_sync(0xffffffffu, d2.y, o);
        d2.z += __shfl_xor_sync(0xffffffffu, d2.z, o);
        d2.w += __shfl_xor_sync(0xffffffffu, d2.w, o);
    }
    float4 r1 = make_float4(1.f / d1.x, 1.f / d1.y, 1.f / d1.z, 1.f / d1.w);
    float4 r2 = make_float4(1.f / d2.x, 1.f / d2.y, 1.f / d2.z, 1.f / d2.w);

    float4 acc1 = make_float4(0.f, 0.f, 0.f, 0.f), acc2 = acc1;
    for (int i = beg; i < end; i++) {
        int s = g_col[i];
        float4 w1 = g_alpha[i], w2 = g_alpha2[i];
        const __half* xb1 = g_xhh  + (size_t)s * HC;
        const __half* xb2 = g_xhh2 + (size_t)s * HC;
        uint2 p0 = *(const uint2*)(xb1 + 0 * C + lane * 4);
        uint2 p1 = *(const uint2*)(xb1 + 1 * C + lane * 4);
        uint2 p2 = *(const uint2*)(xb1 + 2 * C + lane * 4);
        uint2 p3 = *(const uint2*)(xb1 + 3 * C + lane * 4);
        uint2 q0 = *(const uint2*)(xb2 + 0 * C + lane * 4);
        uint2 q1 = *(const uint2*)(xb2 + 1 * C + lane * 4);
        uint2 q2 = *(const uint2*)(xb2 + 2 * C + lane * 4);
        uint2 q3 = *(const uint2*)(xb2 + 3 * C + lane * 4);
        float v0 = w1.x * r1.x, v1 = w1.y * r1.y, v2 = w1.z * r1.z, v3 = w1.w * r1.w;
        float u0 = w2.x * r2.x, u1 = w2.y * r2.y, u2 = w2.z * r2.z, u3 = w2.w * r2.w;
        {
            float2 a0 = __half22float2(*(__half2*)&p0.x), b0 = __half22float2(*(__half2*)&p0.y);
            float2 a1 = __half22float2(*(__half2*)&p1.x), b1 = __half22float2(*(__half2*)&p1.y);
            float2 a2 = __half22float2(*(__half2*)&p2.x), b2 = __half22float2(*(__half2*)&p2.y);
            float2 a3 = __half22float2(*(__half2*)&p3.x), b3 = __half22float2(*(__half2*)&p3.y);
            acc1.x += v0 * a0.x + v1 * a1.x + v2 * a2.x + v3 * a3.x;
            acc1.y += v0 * a0.y + v1 * a1.y + v2 * a2.y + v3 * a3.y;
            acc1.z += v0 * b0.x + v1 * b1.x + v2 * b2.x + v3 * b3.x;
            acc1.w += v0 * b0.y + v1 * b1.y + v2 * b2.y + v3 * b3.y;
        }
        {
            float2 a0 = __half22float2(*(__half2*)&q0.x), b0 = __half22float2(*(__half2*)&q0.y);
            float2 a1 = __half22float2(*(__half2*)&q1.x), b1 = __half22float2(*(__half2*)&q1.y);
            float2 a2 = __half22float2(*(__half2*)&q2.x), b2 = __half22float2(*(__half2*)&q2.y);
            float2 a3 = __half22float2(*(__half2*)&q3.x), b3 = __half22float2(*(__half2*)&q3.y);
            acc2.x += u0 * a0.x + u1 * a1.x + u2 * a2.x + u3 * a3.x;
            acc2.y += u0 * a0.y + u1 * a1.y + u2 * a2.y + u3 * a3.y;
            acc2.z += u0 * b0.x + u1 * b1.x + u2 * b2.x + u3 * b3.x;
            acc2.w += u0 * b0.y + u1 * b1.y + u2 * b2.y + u3 * b3.y;
        }
    }

    float4 b1v = *(const float4*)(bias1 + lane * 4);
    float4 brv = *(const float4*)(biasr + lane * 4);
    float4 o1, o2;
    o1.x = acc1.x * 0.25f + b1v.x; o1.y = acc1.y * 0.25f + b1v.y;
    o1.z = acc1.z * 0.25f + b1v.z; o1.w = acc1.w * 0.25f + b1v.w;
    o2.x = acc2.x * 0.25f + brv.x; o2.y = acc2.y * 0.25f + brv.y;
    o2.z = acc2.z * 0.25f + brv.z; o2.w = acc2.w * 0.25f + brv.w;
    *(float4*)(g_h1  + (size_t)node * C + lane * 4) = o1;
    *(float4*)(g_res + (size_t)node * C + lane * 4) = o2;
}

// conv2 aggregation: set-A arrays, adds g_res, writes dout
__global__ void k_agg(const float* __restrict__ bias, float* __restrict__ dout, int n) {
    int node = (blockIdx.x * blockDim.x + threadIdx.x) >> 5;
    int lane = threadIdx.x & 31;
    if (node >= n) return;
    int beg = g_rowptr[node], end = g_rowptr[node + 1];

    float4 adv = *(const float4*)(g_ald + node * H);

    float4 m1 = make_float4(-3.4e38f, -3.4e38f, -3.4e38f, -3.4e38f);
    for (int i = beg + lane; i < end; i += 32) {
        float4 a1 = *(const float4*)(g_als + g_col[i] * H);
        m1 = f4max(m1, make_float4(lrelu(a1.x + adv.x), lrelu(a1.y + adv.y), lrelu(a1.z + adv.z), lrelu(a1.w + adv.w)));
    }
#pragma unroll
    for (int o = 16; o; o >>= 1) {
        m1.x = fmaxf(m1.x, __shfl_xor_sync(0xffffffffu, m1.x, o));
        m1.y = fmaxf(m1.y, __shfl_xor_sync(0xffffffffu, m1.y, o));
        m1.z = fmaxf(m1.z, __shfl_xor_sync(0xffffffffu, m1.z, o));
        m1.w = fmaxf(m1.w, __shfl_xor_sync(0xffffffffu, m1.w, o));
    }

    float4 d1 = make_float4(0.f, 0.f, 0.f, 0.f);
    for (int i = beg + lane; i < end; i += 32) {
        float4 a1 = *(const float4*)(g_als + g_col[i] * H);
        float4 e1 = make_float4(expf(lrelu(a1.x + adv.x) - m1.x), expf(lrelu(a1.y + adv.y) - m1.y),
                                expf(lrelu(a1.z + adv.z) - m1.z), expf(lrelu(a1.w + adv.w) - m1.w));
        g_alpha[i] = e1;
        d1.x += e1.x; d1.y += e1.y; d1.z += e1.z; d1.w += e1.w;
    }
#pragma unroll
    for (int o = 16; o; o >>= 1) {
        d1.x += __shfl_xor_sync(0xffffffffu, d1.x, o);
        d1.y += __shfl_xor_sync(0xffffffffu, d1.y, o);
        d1.z += __shfl_xor_sync(0xffffffffu, d1.z, o);
        d1.w += __shfl_xor_sync(0xffffffffu, d1.w, o);
    }
    float4 rr = make_float4(1.f / d1.x, 1.f / d1.y, 1.f / d1.z, 1.f / d1.w);

    float4 acc = make_float4(0.f, 0.f, 0.f, 0.f);
    for (int i = beg; i < end; i++) {
        int s = g_col[i];
        float4 w4 = g_alpha[i];
        float w0 = w4.x * rr.x, w1 = w4.y * rr.y, w2 = w4.z * rr.z, w3 = w4.w * rr.w;
        const __half* xb = g_xhh + (size_t)s * HC;
        uint2 q0 = *(const uint2*)(xb + 0 * C + lane * 4);
        uint2 q1 = *(const uint2*)(xb + 1 * C + lane * 4);
        uint2 q2 = *(const uint2*)(xb + 2 * C + lane * 4);
        uint2 q3 = *(const uint2*)(xb + 3 * C + lane * 4);
        float2 a0 = __half22float2(*(__half2*)&q0.x), b0 = __half22float2(*(__half2*)&q0.y);
        float2 a1 = __half22float2(*(__half2*)&q1.x), b1 = __half22float2(*(__half2*)&q1.y);
        float2 a2 = __half22float2(*(__half2*)&q2.x), b2 = __half22float2(*(__half2*)&q2.y);
        float2 a3 = __half22float2(*(__half2*)&q3.x), b3 = __half22float2(*(__half2*)&q3.y);
        acc.x += w0 * a0.x + w1 * a1.x + w2 * a2.x + w3 * a3.x;
        acc.y += w0 * a0.y + w1 * a1.y + w2 * a2.y + w3 * a3.y;
        acc.z += w0 * b0.x + w1 * b1.x + w2 * b2.x + w3 * b3.x;
        acc.w += w0 * b0.y + w1 * b1.y + w2 * b2.y + w3 * b3.y;
    }

    float4 b4 = *(const float4*)(bias + lane * 4);
    float4 a4 = *(const float4*)(g_res + (size_t)node * C + lane * 4);
    float4 o4;
    o4.x = acc.x * 0.25f + b4.x + a4.x;
    o4.y = acc.y * 0.25f + b4.y + a4.y;
    o4.z = acc.z * 0.25f + b4.z + a4.z;
    o4.w = acc.w * 0.25f + b4.w + a4.w;
    *(float4*)(dout + (size_t)node * C + lane * 4) = o4;
}

// ---------------- host side ----------------
extern "C" void kernel_launch(void* const* d_in, const int* in_sizes, int n_in,
                              void* d_out, int out_size) {
    const float* x   = (const float*)d_in[0];
    const int*   ei  = (const int*)d_in[1];     // int32 (JAX x64 disabled)
    const float* W1  = (const float*)d_in[2];
    const float* as1 = (const float*)d_in[3];
    const float* ad1 = (const float*)d_in[4];
    const float* b1  = (const float*)d_in[5];
    const float* W2  = (const float*)d_in[6];
    const float* as2 = (const float*)d_in[7];
    const float* ad2 = (const float*)d_in[8];
    const float* b2  = (const float*)d_in[9];
    const float* Wr  = (const float*)d_in[10];
    const float* asr = (const float*)d_in[11];
    const float* adr = (const float*)d_in[12];
    const float* br  = (const float*)d_in[13];

    int n = in_sizes[0] / C;
    int e = in_sizes[1] / 2;
    int nb = (n + 1023) / 1024;

    cudaFuncSetAttribute(k_gemm_mma, cudaFuncAttributeMaxDynamicSharedMemorySize, SMEM_GEMM);

    // launches 0..4 (CSR, except scatter) — so launch #5 = merged GEMM for ncu
    k_zero_cnt<<<(n + 255) / 256, 256>>>(n);
    k_hist<<<(e + n + 255) / 256, 256>>>(ei, e, n);
    k_scan1<<<nb, 1024>>>(n);
    k_scan2<<<1, 32>>>(nb, n);
    k_scan3<<<(n + 255) / 256, 256>>>(n);

    // launch 5: merged conv1 + conv_r GEMM (8 head-slots)
    dim3 gg1((n + GBM - 1) / GBM, 2 * H);
    k_gemm_mma<<<gg1, 256, SMEM_GEMM>>>(x, W1, as1, ad1, Wr, asr, adr, n, 0);

    k_scatter<<<(e + n + 255) / 256, 256>>>(ei, e, n);

    // combined conv1 + conv_r aggregation
    k_agg2<<<(n * 32 + 255) / 256, 256>>>(b1, br, n);

    // conv2: GEMM from g_h1 (set A slots only), then agg with residual
    dim3 gg2((n + GBM - 1) / GBM, H);
    k_gemm_mma<<<gg2, 256, SMEM_GEMM>>>(nullptr, W2, as2, ad2, Wr, asr, adr, n, 1);
    k_agg<<<(n * 32 + 255) / 256, 256>>>(b2, (float*)d_out, n);
}